// round 1
// baseline (speedup 1.0000x reference)
#include <cuda_runtime.h>
#include <cuda_bf16.h>
#include <math.h>
#include <stdint.h>

#define HID   1024
#define VOCAB 32000
#define BATCH 64
#define NLEAF 32
#define ROWS_FINAL (BATCH * NLEAF)   // 2048
#define BKP 40                        // smem row stride in halves (32 + 8 pad)

// ---------------- static device scratch (no allocations allowed) ----------------
__device__ float g_hA[ROWS_FINAL * HID];            // 8 MB
__device__ float g_hB[ROWS_FINAL * HID];            // 8 MB
__device__ float g_gl[1024 * 3 * HID];              // 12.6 MB
__device__ float g_gr[1024 * 3 * HID];              // 12.6 MB
__device__ float g_logits[(size_t)ROWS_FINAL * VOCAB]; // 262 MB

// ---------------- GEMM: C[M,N] = A[M,K] * B[N,K]^T  (fp32 in, bf16 mma, fp32 out) ----
// Block tile 128x128, BK=32, 8 warps (4 in M, 2 in N), warp tile 32x64.
__global__ __launch_bounds__(256) void gemm_bf16_tn(
    const float* __restrict__ A,   // [M,K] row-major fp32
    const float* __restrict__ B,   // [N,K] row-major fp32
    float* __restrict__ C,         // [M,N] row-major fp32
    int M, int N, int K)
{
    __shared__ __nv_bfloat16 As[128][BKP];
    __shared__ __nv_bfloat16 Bs[128][BKP];

    const int tid  = threadIdx.x;
    const int lane = tid & 31;
    const int warp = tid >> 5;
    const int wm   = warp & 3;    // 0..3 -> rows wm*32
    const int wn   = warp >> 2;   // 0..1 -> cols wn*64
    const int blockM = blockIdx.x * 128;   // M is the FAST grid axis (B-tile L2 reuse)
    const int blockN = blockIdx.y * 128;

    float acc[2][8][4];
#pragma unroll
    for (int mi = 0; mi < 2; ++mi)
#pragma unroll
        for (int nj = 0; nj < 8; ++nj)
#pragma unroll
            for (int q = 0; q < 4; ++q) acc[mi][nj][q] = 0.f;

    const int kTiles = K >> 5;
    for (int kt = 0; kt < kTiles; ++kt) {
        const int k0 = kt << 5;
        // load + convert A tile (128x32 fp32 -> bf16)
#pragma unroll
        for (int i = 0; i < 4; ++i) {
            int idx = tid + (i << 8);
            int r   = idx >> 3;
            int c   = (idx & 7) << 2;
            int grow = blockM + r;
            float4 v = make_float4(0.f, 0.f, 0.f, 0.f);
            if (grow < M) v = *(const float4*)(A + (size_t)grow * K + k0 + c);
            __nv_bfloat162* d2 = (__nv_bfloat162*)&As[r][c];
            d2[0] = __floats2bfloat162_rn(v.x, v.y);
            d2[1] = __floats2bfloat162_rn(v.z, v.w);
        }
        // load + convert B tile (128x32 fp32 -> bf16)
#pragma unroll
        for (int i = 0; i < 4; ++i) {
            int idx = tid + (i << 8);
            int r   = idx >> 3;
            int c   = (idx & 7) << 2;
            int gn  = blockN + r;
            float4 v = make_float4(0.f, 0.f, 0.f, 0.f);
            if (gn < N) v = *(const float4*)(B + (size_t)gn * K + k0 + c);
            __nv_bfloat162* d2 = (__nv_bfloat162*)&Bs[r][c];
            d2[0] = __floats2bfloat162_rn(v.x, v.y);
            d2[1] = __floats2bfloat162_rn(v.z, v.w);
        }
        __syncthreads();

#pragma unroll
        for (int kk = 0; kk < 2; ++kk) {
            uint32_t af[2][4];
#pragma unroll
            for (int mi = 0; mi < 2; ++mi) {
                int row = wm * 32 + mi * 16 + (lane & 15);
                int col = kk * 16 + (lane >> 4) * 8;
                uint32_t addr = (uint32_t)__cvta_generic_to_shared(&As[row][col]);
                asm volatile("ldmatrix.sync.aligned.m8n8.x4.shared.b16 {%0,%1,%2,%3}, [%4];\n"
                             : "=r"(af[mi][0]), "=r"(af[mi][1]), "=r"(af[mi][2]), "=r"(af[mi][3])
                             : "r"(addr));
            }
            uint32_t bfr[8][2];
#pragma unroll
            for (int nj = 0; nj < 8; ++nj) {
                int l    = lane & 15;
                int nrow = wn * 64 + nj * 8 + (l & 7);
                int col  = kk * 16 + (l >> 3) * 8;
                uint32_t addr = (uint32_t)__cvta_generic_to_shared(&Bs[nrow][col]);
                asm volatile("ldmatrix.sync.aligned.m8n8.x2.shared.b16 {%0,%1}, [%2];\n"
                             : "=r"(bfr[nj][0]), "=r"(bfr[nj][1])
                             : "r"(addr));
            }
#pragma unroll
            for (int mi = 0; mi < 2; ++mi)
#pragma unroll
                for (int nj = 0; nj < 8; ++nj)
                    asm volatile(
                        "mma.sync.aligned.m16n8k16.row.col.f32.bf16.bf16.f32 "
                        "{%0,%1,%2,%3}, {%4,%5,%6,%7}, {%8,%9}, {%0,%1,%2,%3};\n"
                        : "+f"(acc[mi][nj][0]), "+f"(acc[mi][nj][1]),
                          "+f"(acc[mi][nj][2]), "+f"(acc[mi][nj][3])
                        : "r"(af[mi][0]), "r"(af[mi][1]), "r"(af[mi][2]), "r"(af[mi][3]),
                          "r"(bfr[nj][0]), "r"(bfr[nj][1]));
        }
        __syncthreads();
    }

    // epilogue: fp32 store
    const int g  = lane >> 2;
    const int tg = lane & 3;
#pragma unroll
    for (int mi = 0; mi < 2; ++mi) {
#pragma unroll
        for (int nj = 0; nj < 8; ++nj) {
            int row0 = blockM + wm * 32 + mi * 16 + g;
            int col  = blockN + wn * 64 + nj * 8 + tg * 2;
            if (row0 < M) {
                float2 v = make_float2(acc[mi][nj][0], acc[mi][nj][1]);
                *(float2*)(C + (size_t)row0 * N + col) = v;
            }
            int row1 = row0 + 8;
            if (row1 < M) {
                float2 v = make_float2(acc[mi][nj][2], acc[mi][nj][3]);
                *(float2*)(C + (size_t)row1 * N + col) = v;
            }
        }
    }
}

// ---------------- GRU gate fusion: parent p -> children 2p (left), 2p+1 (right) ----
__device__ __forceinline__ float sigmoidf_(float x) { return 1.f / (1.f + expf(-x)); }

__global__ void gru_gate_k(
    const float* __restrict__ GL, const float* __restrict__ GR,
    const float* __restrict__ hin,
    const float* __restrict__ bihl, const float* __restrict__ bhhl,
    const float* __restrict__ bihr, const float* __restrict__ bhhr,
    float* __restrict__ hout, int M)
{
    int i = blockIdx.x * blockDim.x + threadIdx.x;
    if (i >= M * HID) return;
    int p = i >> 10;
    int j = i & (HID - 1);
    float h = hin[(size_t)p * HID + j];
    const float* gl = GL + (size_t)p * 3 * HID;
    const float* gr = GR + (size_t)p * 3 * HID;
    {
        float r = sigmoidf_(gl[j] + bhhl[j] + bihl[j]);
        float z = sigmoidf_(gl[HID + j] + bhhl[HID + j] + bihl[HID + j]);
        float n = tanhf(bihl[2 * HID + j] + r * (gl[2 * HID + j] + bhhl[2 * HID + j]));
        hout[(size_t)(2 * p) * HID + j] = (1.f - z) * n + z * h;
    }
    {
        float r = sigmoidf_(gr[j] + bhhr[j] + bihr[j]);
        float z = sigmoidf_(gr[HID + j] + bhhr[HID + j] + bihr[HID + j]);
        float n = tanhf(bihr[2 * HID + j] + r * (gr[2 * HID + j] + bhhr[2 * HID + j]));
        hout[(size_t)(2 * p + 1) * HID + j] = (1.f - z) * n + z * h;
    }
}

// ---------------- log-softmax over V, with transposed [N,B,V] output -------------
__global__ __launch_bounds__(256) void logsoftmax_k(
    const float* __restrict__ logits, const float* __restrict__ bout,
    float* __restrict__ out)
{
    extern __shared__ float srow[];     // VOCAB floats (128 KB)
    __shared__ float s_red[8];
    __shared__ float s_bcast;

    const int row = blockIdx.x;          // = b*32 + n
    const int b   = row >> 5;
    const int n   = row & 31;
    const float* src = logits + (size_t)row * VOCAB;
    float* dst = out + (size_t)(n * BATCH + b) * VOCAB;
    const int t = threadIdx.x;

    float lmax = -1e30f;
    for (int v = t * 4; v < VOCAB; v += 1024) {
        float4 x  = *(const float4*)(src + v);
        float4 bb = *(const float4*)(bout + v);
        x.x += bb.x; x.y += bb.y; x.z += bb.z; x.w += bb.w;
        *(float4*)(srow + v) = x;
        lmax = fmaxf(lmax, fmaxf(fmaxf(x.x, x.y), fmaxf(x.z, x.w)));
    }
#pragma unroll
    for (int o = 16; o; o >>= 1) lmax = fmaxf(lmax, __shfl_xor_sync(0xffffffffu, lmax, o));
    if ((t & 31) == 0) s_red[t >> 5] = lmax;
    __syncthreads();
    if (t == 0) {
        float m = s_red[0];
#pragma unroll
        for (int i = 1; i < 8; ++i) m = fmaxf(m, s_red[i]);
        s_bcast = m;
    }
    __syncthreads();
    const float m = s_bcast;

    float ls = 0.f;
    for (int v = t * 4; v < VOCAB; v += 1024) {
        float4 x = *(const float4*)(srow + v);
        ls += expf(x.x - m) + expf(x.y - m) + expf(x.z - m) + expf(x.w - m);
    }
#pragma unroll
    for (int o = 16; o; o >>= 1) ls += __shfl_xor_sync(0xffffffffu, ls, o);
    if ((t & 31) == 0) s_red[t >> 5] = ls;
    __syncthreads();
    if (t == 0) {
        float s = 0.f;
#pragma unroll
        for (int i = 0; i < 8; ++i) s += s_red[i];
        s_bcast = m + logf(s);
    }
    __syncthreads();
    const float lse = s_bcast;

    for (int v = t * 4; v < VOCAB; v += 1024) {
        float4 x = *(const float4*)(srow + v);
        x.x -= lse; x.y -= lse; x.z -= lse; x.w -= lse;
        *(float4*)(dst + v) = x;
    }
}

// ---------------- host orchestration -------------------------------------------
extern "C" void kernel_launch(void* const* d_in, const int* in_sizes, int n_in,
                              void* d_out, int out_size)
{
    (void)in_sizes; (void)n_in; (void)out_size;
    const float* enc  = (const float*)d_in[0];
    const float* Whhl = (const float*)d_in[1];
    const float* bihl = (const float*)d_in[2];
    const float* bhhl = (const float*)d_in[3];
    const float* Whhr = (const float*)d_in[4];
    const float* bihr = (const float*)d_in[5];
    const float* bhhr = (const float*)d_in[6];
    const float* Wout = (const float*)d_in[7];
    const float* bout = (const float*)d_in[8];

    float *hA, *hB, *gl, *gr, *lg;
    cudaGetSymbolAddress((void**)&hA, g_hA);
    cudaGetSymbolAddress((void**)&hB, g_hB);
    cudaGetSymbolAddress((void**)&gl, g_gl);
    cudaGetSymbolAddress((void**)&gr, g_gr);
    cudaGetSymbolAddress((void**)&lg, g_logits);

    const float* hin = enc;
    float* bufs[2] = {hA, hB};
    int M = BATCH;
    for (int d = 0; d < 5; ++d) {
        dim3 grid((M + 127) / 128, (3 * HID) / 128);
        gemm_bf16_tn<<<grid, 256>>>(hin, Whhl, gl, M, 3 * HID, HID);
        gemm_bf16_tn<<<grid, 256>>>(hin, Whhr, gr, M, 3 * HID, HID);
        float* hout = bufs[d & 1];
        int thr = M * HID;
        gru_gate_k<<<(thr + 255) / 256, 256>>>(gl, gr, hin, bihl, bhhl, bihr, bhhr, hout, M);
        hin = hout;
        M <<= 1;
    }
    // final: hin == g_hA, M == 2048
    dim3 grid2(ROWS_FINAL / 128, VOCAB / 128);
    gemm_bf16_tn<<<grid2, 256>>>(hin, Wout, lg, ROWS_FINAL, VOCAB, HID);

    cudaFuncSetAttribute(logsoftmax_k, cudaFuncAttributeMaxDynamicSharedMemorySize,
                         VOCAB * (int)sizeof(float));
    logsoftmax_k<<<ROWS_FINAL, 256, VOCAB * sizeof(float)>>>(lg, bout, (float*)d_out);
}